// round 7
// baseline (speedup 1.0000x reference)
#include <cuda_runtime.h>
#include <cuda_bf16.h>

// Problem collapses analytically:
//   - quantum_expectation ≡ 0 (the uniform state 2^{-n/2}·1 is invariant under
//     RX on any qubit: both amplitudes of each (s0,s1) pair are equal, so
//     RX yields (c+ms)·s = e^{-i theta/2}·s, a global phase, for ANY theta;
//     the CX chain is a basis permutation, also uniformity-preserving.
//     Hence p1 = 0.5 and 2*p1 - 1 = 0 for every batch element.)
//   - output = 0.5 * mean(sigmoid(conv2d_valid_4x4(data, w) + b)).
//
// Single fused kernel: 256 CTAs (one per 64x64 image). Image -> smem, 4x4 conv
// over 61x61 valid outputs, sigmoid, block tree-reduction -> g_partials[img].
// The last CTA to finish (atomicInc ticket) reduces the 256 partials in a
// FIXED tree order (deterministic independent of arrival order), scales, and
// broadcasts to d_out. atomicInc wraps the counter back to 0, so the kernel is
// replay-safe under CUDA graph capture with no host-side reset.
//
// Cost model: ~15.2M lane-FMAs -> ~0.9 us compute; 4 MB input at LTS cap
// (~6300 B/cyc) -> ~0.4 us; kernel is latency/launch-bound -> single launch.

#define IMGS 256
#define IMG_W 64
#define IMG_H 64
#define OUT_W 61                      // 64 - 4 + 1
#define OUT_PER_IMG (OUT_W * OUT_W)   // 3721
#define NTHREADS 256

__device__ float        g_partials[IMGS];
__device__ unsigned int g_ticket = 0;

__global__ __launch_bounds__(NTHREADS)
void conv_hybrid_fused_kernel(const float* __restrict__ data,
                              const float* __restrict__ conv_w,
                              const float* __restrict__ conv_b,
                              float* __restrict__ out, int out_size)
{
    __shared__ float tile[IMG_H * IMG_W];   // 16 KB
    __shared__ float red[NTHREADS];
    __shared__ bool  is_last;

    const int img = blockIdx.x;
    const int tid = threadIdx.x;
    const float* __restrict__ src = data + (size_t)img * (IMG_H * IMG_W);

    // Stage image into shared memory with 128-bit loads (4096 floats = 1024
    // float4 -> 4 per thread, issued back-to-back for MLP).
    const float4* __restrict__ src4 = reinterpret_cast<const float4*>(src);
    float4* tile4 = reinterpret_cast<float4*>(tile);
    #pragma unroll
    for (int i = 0; i < (IMG_H * IMG_W) / (4 * NTHREADS); i++)
        tile4[tid + i * NTHREADS] = src4[tid + i * NTHREADS];

    // Weights -> registers (16 floats, L1/const broadcast) while loads fly.
    float w[16];
    #pragma unroll
    for (int k = 0; k < 16; k++) w[k] = conv_w[k];
    const float bias = conv_b[0];

    __syncthreads();

    // Each thread handles strided conv outputs; 3721/256 ~= 14.5 per thread.
    float acc = 0.0f;
    for (int idx = tid; idx < OUT_PER_IMG; idx += NTHREADS) {
        const int r = idx / OUT_W;
        const int c = idx - r * OUT_W;
        const float* __restrict__ t = &tile[r * IMG_W + c];
        float s = bias;
        #pragma unroll
        for (int ky = 0; ky < 4; ky++) {
            #pragma unroll
            for (int kx = 0; kx < 4; kx++)
                s = fmaf(t[ky * IMG_W + kx], w[ky * 4 + kx], s);
        }
        acc += 1.0f / (1.0f + __expf(-s));   // sigmoid
    }

    // Deterministic block tree reduction (order is fixed by tid, not timing).
    red[tid] = acc;
    __syncthreads();
    #pragma unroll
    for (int off = NTHREADS / 2; off > 0; off >>= 1) {
        if (tid < off) red[tid] += red[tid + off];
        __syncthreads();
    }

    if (tid == 0) {
        g_partials[img] = red[0];
        __threadfence();   // release: partial visible at device scope
        // Wraps to 0 after reaching IMGS-1 -> counter is 0 again next replay.
        unsigned int old = atomicInc(&g_ticket, IMGS - 1);
        is_last = (old == IMGS - 1);
    }
    __syncthreads();

    if (!is_last) return;

    // Final reduction by the last CTA: 256 partials, one per thread.
    // __ldcg bypasses (incoherent) L1 so we observe all CTAs' released stores.
    // Double accumulation in a fixed tree order -> fully deterministic.
    __shared__ double dred[NTHREADS];
    dred[tid] = (double)__ldcg(&g_partials[tid]);
    __syncthreads();
    #pragma unroll
    for (int off = NTHREADS / 2; off > 0; off >>= 1) {
        if (tid < off) dred[tid] += dred[tid + off];
        __syncthreads();
    }

    const float v = (float)(0.5 * (dred[0] / (double)(IMGS * OUT_PER_IMG)));
    for (int i = tid; i < out_size; i += NTHREADS)
        out[i] = v;
}

extern "C" void kernel_launch(void* const* d_in, const int* in_sizes, int n_in,
                              void* d_out, int out_size)
{
    const float* data   = (const float*)d_in[0];   // 256*1*64*64
    const float* conv_w = (const float*)d_in[1];   // 16
    const float* conv_b = (const float*)d_in[2];   // 1
    float* out = (float*)d_out;

    conv_hybrid_fused_kernel<<<IMGS, NTHREADS>>>(data, conv_w, conv_b, out, out_size);
}

// round 13
// speedup vs baseline: 1.1599x; 1.1599x over previous
#include <cuda_runtime.h>
#include <cuda_bf16.h>

// Problem collapses analytically:
//   - quantum_expectation ≡ 0 (uniform state invariant under RX up to global
//     phase; CX chain is a permutation) -> p1 = 0.5, 2*p1-1 = 0 exactly.
//   - output = 0.5 * mean(sigmoid(conv2d_valid_4x4(data, w) + b)).
//
// R7 ncu: occ 20.7%, issue 22%, all pipes idle -> latency-bound, too few warps,
// and 240 scalar LDS per thread. Fix: 4 row-bands per image (1024 CTAs x 128
// thr -> ~7 CTAs/SM) + vectorized LDS.128 window loads (12 per 8 outputs).

#define IMGS        256
#define IMG_W       64
#define IMG_H       64
#define OUT_W       61               // 64 - 4 + 1
#define OUT_H       61
#define OUT_PER_IMG (OUT_W * OUT_H)  // 3721
#define BANDS       4
#define BAND_ROWS   16               // output rows per band (last band: 13)
#define NBLOCKS     (IMGS * BANDS)   // 1024
#define NTHREADS    128
#define STAGE_MAX   19               // 16 output rows + 3 halo

__device__ float        g_partials[NBLOCKS];
__device__ unsigned int g_ticket = 0;

__global__ __launch_bounds__(NTHREADS)
void conv_hybrid_fused_kernel(const float* __restrict__ data,
                              const float* __restrict__ conv_w,
                              const float* __restrict__ conv_b,
                              float* __restrict__ out, int out_size)
{
    // +4 floats pad: seg-7 threads' third LDS.128 may touch cols 64..67 of the
    // last staged row (values unused; pad keeps the access in-bounds).
    __shared__ float tile[STAGE_MAX * IMG_W + 4];
    __shared__ float red[NTHREADS];
    __shared__ bool  is_last;

    const int blk  = blockIdx.x;
    const int img  = blk >> 2;          // blk / BANDS
    const int band = blk & 3;           // blk % BANDS
    const int tid  = threadIdx.x;

    const int r0     = band * BAND_ROWS;                 // first output row
    const int nrows  = (band < 3) ? BAND_ROWS : (OUT_H - 3 * BAND_ROWS); // 16/13
    const int nstage = min(STAGE_MAX, IMG_H - r0);       // 19,19,19,16

    // Stage band rows [r0, r0+nstage) into smem with float4 loads.
    {
        const float4* __restrict__ src4 =
            reinterpret_cast<const float4*>(data + (size_t)img * (IMG_H * IMG_W)
                                                 + (size_t)r0 * IMG_W);
        float4* tile4 = reinterpret_cast<float4*>(tile);
        const int n4 = nstage * (IMG_W / 4);             // 304 or 256
        #pragma unroll
        for (int i = tid; i < n4; i += NTHREADS)
            tile4[i] = src4[i];
    }

    // Weights -> registers while the stage loads are in flight.
    float w[16];
    #pragma unroll
    for (int k = 0; k < 16; k++) w[k] = conv_w[k];
    const float bias = conv_b[0];

    __syncthreads();

    // Thread -> (local output row, 8-col segment):
    //   row = tid/8 (0..15), seg = tid%8, cols [8*seg, 8*seg+8).
    const int lrow = tid >> 3;
    const int cbase = (tid & 7) << 3;

    float acc = 0.0f;
    if (lrow < nrows) {
        // Load the 4 x 12 input window as 12 x LDS.128 (conflict-free).
        float v[4][12];
        #pragma unroll
        for (int ky = 0; ky < 4; ky++) {
            const float4* rowp =
                reinterpret_cast<const float4*>(&tile[(lrow + ky) * IMG_W + cbase]);
            #pragma unroll
            for (int m = 0; m < 3; m++) {
                float4 q = rowp[m];
                v[ky][4 * m + 0] = q.x;
                v[ky][4 * m + 1] = q.y;
                v[ky][4 * m + 2] = q.z;
                v[ky][4 * m + 3] = q.w;
            }
        }
        #pragma unroll
        for (int j = 0; j < 8; j++) {
            if (cbase + j < OUT_W) {          // only seg 7 clips (cols 61..63)
                float s = bias;
                #pragma unroll
                for (int ky = 0; ky < 4; ky++) {
                    #pragma unroll
                    for (int kx = 0; kx < 4; kx++)
                        s = fmaf(v[ky][j + kx], w[ky * 4 + kx], s);
                }
                acc += 1.0f / (1.0f + __expf(-s));   // sigmoid
            }
        }
    }

    // Deterministic block tree reduction (order fixed by tid).
    red[tid] = acc;
    __syncthreads();
    #pragma unroll
    for (int off = NTHREADS / 2; off > 0; off >>= 1) {
        if (tid < off) red[tid] += red[tid + off];
        __syncthreads();
    }

    if (tid == 0) {
        g_partials[blk] = red[0];
        __threadfence();                         // release partial
        // Wraps to 0 after NBLOCKS-1 -> replay-safe under graph capture.
        unsigned int old = atomicInc(&g_ticket, NBLOCKS - 1);
        is_last = (old == NBLOCKS - 1);
    }
    __syncthreads();

    if (!is_last) return;

    // Last CTA: reduce 1024 partials, fixed order, double accumulation.
    // __ldcg bypasses (incoherent) L1 to observe all CTAs' released stores.
    __shared__ double dred[NTHREADS];
    double d = 0.0;
    #pragma unroll
    for (int k = 0; k < NBLOCKS / NTHREADS; k++)
        d += (double)__ldcg(&g_partials[tid + k * NTHREADS]);
    dred[tid] = d;
    __syncthreads();
    #pragma unroll
    for (int off = NTHREADS / 2; off > 0; off >>= 1) {
        if (tid < off) dred[tid] += dred[tid + off];
        __syncthreads();
    }

    const float v = (float)(0.5 * (dred[0] / (double)(IMGS * OUT_PER_IMG)));
    for (int i = tid; i < out_size; i += NTHREADS)
        out[i] = v;
}

extern "C" void kernel_launch(void* const* d_in, const int* in_sizes, int n_in,
                              void* d_out, int out_size)
{
    const float* data   = (const float*)d_in[0];   // 256*1*64*64
    const float* conv_w = (const float*)d_in[1];   // 16
    const float* conv_b = (const float*)d_in[2];   // 1
    float* out = (float*)d_out;

    conv_hybrid_fused_kernel<<<NBLOCKS, NTHREADS>>>(data, conv_w, conv_b, out, out_size);
}

// round 14
// speedup vs baseline: 1.1840x; 1.0208x over previous
#include <cuda_runtime.h>
#include <cuda_bf16.h>

// Problem collapses analytically:
//   - quantum_expectation ≡ 0 (uniform state invariant under RX up to global
//     phase; CX chain is a permutation) -> p1 = 0.5, 2*p1-1 = 0 exactly.
//   - output = 0.5 * mean(sigmoid(conv2d_valid_4x4(data, w) + b)).
//
// R13 post-mortem: occ hit its grid-limited ceiling (37%) but dur barely moved
// -> total thread count and per-thread critical path are the limiters.
// R14: 4 outputs/thread (262K threads -> ~55 warps/SM), direct coalesced
// LDG.128 window loads (no smem stage, no stage barrier), shfl reductions
// (1 barrier instead of 7).

#define IMGS        256
#define IMG_W       64
#define IMG_H       64
#define OUT_W       61               // 64 - 4 + 1
#define OUT_H       61
#define OUT_PER_IMG (OUT_W * OUT_H)  // 3721
#define BANDS       4
#define BAND_ROWS   16               // output rows per band (last band: 13)
#define NBLOCKS     (IMGS * BANDS)   // 1024
#define NTHREADS    256
#define NWARPS      (NTHREADS / 32)

__device__ float        g_partials[NBLOCKS];
__device__ unsigned int g_ticket = 0;

__global__ __launch_bounds__(NTHREADS)
void conv_hybrid_fused_kernel(const float* __restrict__ data,
                              const float* __restrict__ conv_w,
                              const float* __restrict__ conv_b,
                              float* __restrict__ out, int out_size)
{
    __shared__ float  wsum[NWARPS];
    __shared__ double dsum[NWARPS];
    __shared__ float  final_v;
    __shared__ bool   is_last;

    const int blk  = blockIdx.x;
    const int img  = blk >> 2;           // blk / BANDS
    const int band = blk & 3;            // blk % BANDS
    const int tid  = threadIdx.x;
    const int lane = tid & 31;
    const int wid  = tid >> 5;

    const int r0    = band * BAND_ROWS;
    const int nrows = (band < 3) ? BAND_ROWS : (OUT_H - 3 * BAND_ROWS); // 16/13

    // Thread -> (local row, 4-col segment): lrow = tid/16, cbase = 4*(tid%16).
    const int lrow  = tid >> 4;          // 0..15
    const int cbase = (tid & 15) << 2;   // 0,4,...,60

    // Weights -> registers (L1/const broadcast).
    float w[16];
    #pragma unroll
    for (int k = 0; k < 16; k++) w[k] = conv_w[k];
    const float bias = conv_b[0];

    float acc = 0.0f;
    if (lrow < nrows) {
        const float* __restrict__ base =
            data + (size_t)img * (IMG_H * IMG_W) + (size_t)(r0 + lrow) * IMG_W;
        // Second float4: cols cbase+4..cbase+7. For cbase==60 that would cross
        // the row (and, on the very last row/image, the buffer) -> clamp to 56.
        // The clamped values only feed outputs 61..63, which are clipped below;
        // output 60 uses only the first float4 (cols 60..63).
        const int c2 = (cbase == 60) ? 56 : cbase + 4;

        // 4x8 input window via 8 coalesced LDG.128 (lanes 0-15: row r span
        // [0,256)B contiguous; lanes 16-31: row r+1).
        float v[4][8];
        #pragma unroll
        for (int ky = 0; ky < 4; ky++) {
            float4 a = *reinterpret_cast<const float4*>(base + ky * IMG_W + cbase);
            float4 b = *reinterpret_cast<const float4*>(base + ky * IMG_W + c2);
            v[ky][0] = a.x; v[ky][1] = a.y; v[ky][2] = a.z; v[ky][3] = a.w;
            v[ky][4] = b.x; v[ky][5] = b.y; v[ky][6] = b.z; v[ky][7] = b.w;
        }

        #pragma unroll
        for (int j = 0; j < 4; j++) {
            if (cbase + j < OUT_W) {     // only seg 15 clips (cols 61..63)
                float s = bias;
                #pragma unroll
                for (int ky = 0; ky < 4; ky++) {
                    #pragma unroll
                    for (int kx = 0; kx < 4; kx++)
                        s = fmaf(v[ky][j + kx], w[ky * 4 + kx], s);
                }
                acc += 1.0f / (1.0f + __expf(-s));   // sigmoid
            }
        }
    }

    // Warp shfl reduction (fixed order -> deterministic), then one barrier.
    #pragma unroll
    for (int off = 16; off > 0; off >>= 1)
        acc += __shfl_down_sync(0xFFFFFFFFu, acc, off);
    if (lane == 0) wsum[wid] = acc;
    __syncthreads();

    if (tid == 0) {
        float s = 0.0f;
        #pragma unroll
        for (int i = 0; i < NWARPS; i++) s += wsum[i];   // fixed order
        g_partials[blk] = s;
        __threadfence();                 // release partial at device scope
        // Wraps to 0 after NBLOCKS-1 -> replay-safe under graph capture.
        unsigned int old = atomicInc(&g_ticket, NBLOCKS - 1);
        is_last = (old == NBLOCKS - 1);
    }
    __syncthreads();

    if (!is_last) return;

    // Last CTA: reduce 1024 partials (4 per thread, __ldcg to bypass
    // incoherent L1), fixed-order double accumulation -> deterministic.
    double d = 0.0;
    #pragma unroll
    for (int k = 0; k < NBLOCKS / NTHREADS; k++)
        d += (double)__ldcg(&g_partials[tid + k * NTHREADS]);
    #pragma unroll
    for (int off = 16; off > 0; off >>= 1)
        d += __shfl_down_sync(0xFFFFFFFFu, d, off);
    if (lane == 0) dsum[wid] = d;
    __syncthreads();

    if (tid == 0) {
        double t = 0.0;
        #pragma unroll
        for (int i = 0; i < NWARPS; i++) t += dsum[i];   // fixed order
        final_v = (float)(0.5 * (t / (double)(IMGS * OUT_PER_IMG)));
    }
    __syncthreads();

    const float v = final_v;
    for (int i = tid; i < out_size; i += NTHREADS)
        out[i] = v;
}

extern "C" void kernel_launch(void* const* d_in, const int* in_sizes, int n_in,
                              void* d_out, int out_size)
{
    const float* data   = (const float*)d_in[0];   // 256*1*64*64
    const float* conv_w = (const float*)d_in[1];   // 16
    const float* conv_b = (const float*)d_in[2];   // 1
    float* out = (float*)d_out;

    conv_hybrid_fused_kernel<<<NBLOCKS, NTHREADS>>>(data, conv_w, conv_b, out, out_size);
}

// round 15
// speedup vs baseline: 1.1875x; 1.0030x over previous
#include <cuda_runtime.h>
#include <cuda_bf16.h>

// Problem collapses analytically:
//   - quantum_expectation ≡ 0 (uniform state invariant under RX up to global
//     phase; CX chain is a permutation) -> p1 = 0.5, 2*p1-1 = 0 exactly.
//   - output = 0.5 * mean(sigmoid(conv2d_valid_4x4(data, w) + b)).
//
// R14 post-mortem: regs=60 capped occupancy at 4 CTAs/SM; dur invariant
// ~11us across designs -> exposed-latency bound. R15: streaming conv
// (4 accumulators, row regs recycled) + __launch_bounds__(256,6) to reach
// 6 CTAs/SM (48 warps), loads interleaved with FMAs, leaner epilogue.

#define IMGS        256
#define IMG_W       64
#define IMG_H       64
#define OUT_W       61               // 64 - 4 + 1
#define OUT_H       61
#define OUT_PER_IMG (OUT_W * OUT_H)  // 3721
#define BANDS       4
#define BAND_ROWS   16               // output rows per band (last band: 13)
#define NBLOCKS     (IMGS * BANDS)   // 1024
#define NTHREADS    256
#define NWARPS      (NTHREADS / 32)

__device__ float        g_partials[NBLOCKS];
__device__ unsigned int g_ticket = 0;

__global__ __launch_bounds__(NTHREADS, 6)
void conv_hybrid_fused_kernel(const float* __restrict__ data,
                              const float* __restrict__ conv_w,
                              const float* __restrict__ conv_b,
                              float* __restrict__ out, int out_size)
{
    __shared__ float  wsum[NWARPS];
    __shared__ double dsum[NWARPS];
    __shared__ float  final_v;
    __shared__ bool   is_last;

    const int blk  = blockIdx.x;
    const int img  = blk >> 2;           // blk / BANDS
    const int band = blk & 3;            // blk % BANDS
    const int tid  = threadIdx.x;
    const int lane = tid & 31;
    const int wid  = tid >> 5;

    const int r0    = band * BAND_ROWS;
    const int nrows = (band < 3) ? BAND_ROWS : (OUT_H - 3 * BAND_ROWS); // 16/13

    // Thread -> (local row, 4-col segment): lrow = tid/16, cbase = 4*(tid%16).
    const int lrow  = tid >> 4;          // 0..15
    const int cbase = (tid & 15) << 2;   // 0,4,...,60

    // Weights -> registers (L1/const broadcast).
    float w[16];
    #pragma unroll
    for (int k = 0; k < 16; k++) w[k] = conv_w[k];
    const float bias = conv_b[0];

    float acc = 0.0f;
    if (lrow < nrows) {
        const float* __restrict__ base =
            data + (size_t)img * (IMG_H * IMG_W) + (size_t)(r0 + lrow) * IMG_W;
        // Second float4 covers cols cbase+4..cbase+7; for cbase==60 clamp to
        // 56 (stays in-row/in-bounds). Clamped values only feed outputs
        // 61..63, which are clipped below; output 60 uses cols 60..63 only.
        const int c2 = (cbase == 60) ? 56 : cbase + 4;

        // Streaming conv: per kernel-row load 2 coalesced LDG.128, fold into
        // 4 accumulators, recycle the row registers (keeps regs <= 42).
        float s0 = bias, s1 = bias, s2 = bias, s3 = bias;
        #pragma unroll
        for (int ky = 0; ky < 4; ky++) {
            const float4 a = *reinterpret_cast<const float4*>(base + ky * IMG_W + cbase);
            const float4 b = *reinterpret_cast<const float4*>(base + ky * IMG_W + c2);
            const float r0f = a.x, r1f = a.y, r2f = a.z, r3f = a.w;
            const float r4f = b.x, r5f = b.y, r6f = b.z;
            const float w0 = w[ky * 4 + 0], w1 = w[ky * 4 + 1];
            const float w2 = w[ky * 4 + 2], w3 = w[ky * 4 + 3];
            s0 = fmaf(r0f, w0, s0); s0 = fmaf(r1f, w1, s0);
            s0 = fmaf(r2f, w2, s0); s0 = fmaf(r3f, w3, s0);
            s1 = fmaf(r1f, w0, s1); s1 = fmaf(r2f, w1, s1);
            s1 = fmaf(r3f, w2, s1); s1 = fmaf(r4f, w3, s1);
            s2 = fmaf(r2f, w0, s2); s2 = fmaf(r3f, w1, s2);
            s2 = fmaf(r4f, w2, s2); s2 = fmaf(r5f, w3, s2);
            s3 = fmaf(r3f, w0, s3); s3 = fmaf(r4f, w1, s3);
            s3 = fmaf(r5f, w2, s3); s3 = fmaf(r6f, w3, s3);
        }

        acc  = 1.0f / (1.0f + __expf(-s0));            // col cbase   (<61 always)
        if (cbase + 1 < OUT_W) acc += 1.0f / (1.0f + __expf(-s1));
        if (cbase + 2 < OUT_W) acc += 1.0f / (1.0f + __expf(-s2));
        if (cbase + 3 < OUT_W) acc += 1.0f / (1.0f + __expf(-s3));
    }

    // Warp shfl reduction (fixed order -> deterministic), then one barrier.
    #pragma unroll
    for (int off = 16; off > 0; off >>= 1)
        acc += __shfl_down_sync(0xFFFFFFFFu, acc, off);
    if (lane == 0) wsum[wid] = acc;
    __syncthreads();

    if (tid == 0) {
        float s = 0.0f;
        #pragma unroll
        for (int i = 0; i < NWARPS; i++) s += wsum[i];   // fixed order
        g_partials[blk] = s;
        __threadfence();                 // release partial at device scope
        // Wraps to 0 after NBLOCKS-1 -> replay-safe under graph capture.
        unsigned int old = atomicInc(&g_ticket, NBLOCKS - 1);
        is_last = (old == NBLOCKS - 1);
    }
    __syncthreads();

    if (!is_last) return;

    // Last CTA: 1024 partials as 256 x LDG.128 (one per thread, L2-level to
    // observe released stores), fixed-order double accumulation.
    double d;
    {
        const float4 p = __ldcg(reinterpret_cast<const float4*>(&g_partials[tid << 2]));
        d = ((double)p.x + (double)p.y) + ((double)p.z + (double)p.w);
    }
    #pragma unroll
    for (int off = 16; off > 0; off >>= 1)
        d += __shfl_down_sync(0xFFFFFFFFu, d, off);
    if (lane == 0) dsum[wid] = d;
    __syncthreads();

    if (tid == 0) {
        double t = 0.0;
        #pragma unroll
        for (int i = 0; i < NWARPS; i++) t += dsum[i];   // fixed order
        final_v = (float)(0.5 * (t / (double)(IMGS * OUT_PER_IMG)));
    }
    __syncthreads();

    const float v = final_v;
    for (int i = tid; i < out_size; i += NTHREADS)
        out[i] = v;
}

extern "C" void kernel_launch(void* const* d_in, const int* in_sizes, int n_in,
                              void* d_out, int out_size)
{
    const float* data   = (const float*)d_in[0];   // 256*1*64*64
    const float* conv_w = (const float*)d_in[1];   // 16
    const float* conv_b = (const float*)d_in[2];   // 1
    float* out = (float*)d_out;

    conv_hybrid_fused_kernel<<<NBLOCKS, NTHREADS>>>(data, conv_w, conv_b, out, out_size);
}